// round 14
// baseline (speedup 1.0000x reference)
#include <cuda_runtime.h>
#include <cuda_bf16.h>
#include <cstdint>

#define NN 50000
#define HH 128
#define RR 6
#define EE 800000
#define LL 3
#define KK 3

#define NT 391                     // row tiles of 128
#define IMG_ELEMS ((size_t)NT * 2 * 8192)   // bf16 elems per split image (hi or lo)
#define NHE ((size_t)NN * HH)
#define PROP_BLOCKS 6250           // NN*32/256

// total B chunks: 18 cheb GEMMs * 6 + proj 12 + cls1 2 = 122
#define NCH_TOTAL 122

// ---------------- static device scratch ----------------
__device__ __align__(16) static float g_emb[(size_t)RR * NHE];
__device__ __align__(16) static float g_txF[(size_t)RR * NHE];
__device__ __align__(16) static float g_hAf[(size_t)RR * NHE];
__device__ __align__(16) static float g_hBf[(size_t)RR * NHE];
__device__ static int   g_deg[RR * NN];
__device__ static int   g_cnt[RR * NN];
__device__ static int   g_rp[RR * NN + 1];
__device__ static int   g_cur[RR * NN];
__device__ __align__(16) static int2 g_pe[(size_t)RR * EE];   // packed {src, dinv[src]}
__device__ static float g_dinv[RR * NN];
__device__ static int   g_bsums[1024];
__device__ __align__(16) static __nv_bfloat16 g_Bhi[(size_t)NCH_TOTAL * 8192];
__device__ __align__(16) static __nv_bfloat16 g_Blo[(size_t)NCH_TOTAL * 8192];
__device__ __align__(16) static __nv_bfloat16 g_xs_hi[IMG_ELEMS], g_xs_lo[IMG_ELEMS];
// per-relation split images: [rel][buf: 0 txh,1 txl,2 tx2h,3 tx2l,4 hAh,5 hAl,6 hBh,7 hBl]
__device__ __align__(16) static __nv_bfloat16 g_rimg[(size_t)RR * 8 * IMG_ELEMS];
__device__ __align__(16) static __nv_bfloat16 g_es_hi[(size_t)RR * IMG_ELEMS];
__device__ __align__(16) static __nv_bfloat16 g_es_lo[(size_t)RR * IMG_ELEMS];

#define SW128(off) ((off) ^ (((off) >> 3) & 0x70))

__device__ __forceinline__ uint32_t smem_u32(const void* p) {
    uint32_t a;
    asm("{ .reg .u64 t; cvta.to.shared.u64 t, %1; cvt.u32.u64 %0, t; }" : "=r"(a) : "l"(p));
    return a;
}
__device__ __forceinline__ void ldsm4(uint32_t* r, uint32_t addr) {
    asm volatile("ldmatrix.sync.aligned.m8n8.x4.shared.b16 {%0,%1,%2,%3}, [%4];"
                 : "=r"(r[0]), "=r"(r[1]), "=r"(r[2]), "=r"(r[3]) : "r"(addr));
}
__device__ __forceinline__ void mma16816(float* c, const uint32_t* a, uint32_t b0, uint32_t b1) {
    asm volatile("mma.sync.aligned.m16n8k16.row.col.f32.bf16.bf16.f32 "
                 "{%0,%1,%2,%3}, {%4,%5,%6,%7}, {%8,%9}, {%0,%1,%2,%3};"
                 : "+f"(c[0]), "+f"(c[1]), "+f"(c[2]), "+f"(c[3])
                 : "r"(a[0]), "r"(a[1]), "r"(a[2]), "r"(a[3]), "r"(b0), "r"(b1));
}
__device__ __forceinline__ void cpa16(uint32_t s, const void* g) {
    asm volatile("cp.async.cg.shared.global [%0], [%1], 16;" :: "r"(s), "l"(g));
}

__device__ __forceinline__ void split_store4(__nv_bfloat16* hi, __nv_bfloat16* lo,
                                             size_t imgByte, int mloc, int kk,
                                             float vx, float vy, float vz, float vw) {
    __nv_bfloat162 h0, h1, l0, l1;
    h0.x = __float2bfloat16(vx); h0.y = __float2bfloat16(vy);
    h1.x = __float2bfloat16(vz); h1.y = __float2bfloat16(vw);
    l0.x = __float2bfloat16(vx - __bfloat162float(h0.x));
    l0.y = __float2bfloat16(vy - __bfloat162float(h0.y));
    l1.x = __float2bfloat16(vz - __bfloat162float(h1.x));
    l1.y = __float2bfloat16(vw - __bfloat162float(h1.y));
    uint32_t off = SW128((uint32_t)(mloc * 128 + kk * 2));
    uint2 hv, lv;
    hv.x = *(uint32_t*)&h0; hv.y = *(uint32_t*)&h1;
    lv.x = *(uint32_t*)&l0; lv.y = *(uint32_t*)&l1;
    *(uint2*)((char*)hi + imgByte + off) = hv;
    *(uint2*)((char*)lo + imgByte + off) = lv;
}

// ---------------- CSR build ----------------
__global__ void zero2_kernel(int* a, int* b, int n) {
    int i = blockIdx.x * blockDim.x + threadIdx.x;
    if (i < n) { a[i] = 0; b[i] = 0; }
}
__global__ void count_kernel(const int* __restrict__ ei, int* __restrict__ deg,
                             int* __restrict__ cnt) {
    int idx = blockIdx.x * blockDim.x + threadIdx.x;
    if (idx >= RR * EE) return;
    int r = idx / EE;
    int e = idx - r * EE;
    int src = ei[(size_t)r * 2 * EE + e];
    int dst = ei[(size_t)r * 2 * EE + EE + e];
    atomicAdd(&deg[r * NN + src], 1);
    atomicAdd(&cnt[r * NN + dst], 1);
}
__global__ void dinv_kernel(const int* __restrict__ deg, float* __restrict__ dinv) {
    int i = blockIdx.x * blockDim.x + threadIdx.x;
    if (i >= RR * NN) return;
    int d = deg[i];
    dinv[i] = (d > 0) ? rsqrtf((float)d) : 0.0f;
}
__global__ void scan1_kernel(const int* __restrict__ in, int* __restrict__ out,
                             int* __restrict__ bsums, int n) {
    __shared__ int sh[1024];
    int i = blockIdx.x * 1024 + threadIdx.x;
    int v = (i < n) ? in[i] : 0;
    sh[threadIdx.x] = v;
    __syncthreads();
    for (int off = 1; off < 1024; off <<= 1) {
        int t = (threadIdx.x >= off) ? sh[threadIdx.x - off] : 0;
        __syncthreads();
        sh[threadIdx.x] += t;
        __syncthreads();
    }
    if (i < n) out[i] = sh[threadIdx.x] - v;
    if (threadIdx.x == 1023) bsums[blockIdx.x] = sh[1023];
}
__global__ void scan2_kernel(int* bsums, int nb) {
    __shared__ int sh[512];
    int v = (threadIdx.x < nb) ? bsums[threadIdx.x] : 0;
    sh[threadIdx.x] = v;
    __syncthreads();
    for (int off = 1; off < 512; off <<= 1) {
        int t = (threadIdx.x >= off) ? sh[threadIdx.x - off] : 0;
        __syncthreads();
        sh[threadIdx.x] += t;
        __syncthreads();
    }
    if (threadIdx.x < nb) bsums[threadIdx.x] = sh[threadIdx.x] - v;
}
__global__ void scan3_kernel(int* __restrict__ rp, const int* __restrict__ bsums,
                             int* __restrict__ cur, int n, int total) {
    int i = blockIdx.x * 1024 + threadIdx.x;
    if (i < n) {
        int v = rp[i] + bsums[blockIdx.x];
        rp[i] = v;
        cur[i] = v;
    }
    if (i == 0) rp[n] = total;
}
// fill packed edges: {src, dinv[src]} sorted by dst (CSR order)
__global__ void fill_kernel(const int* __restrict__ ei, int* __restrict__ cur,
                            int2* __restrict__ pe, const float* __restrict__ dinv) {
    int idx = blockIdx.x * blockDim.x + threadIdx.x;
    if (idx >= RR * EE) return;
    int r = idx / EE;
    int e = idx - r * EE;
    int src = ei[(size_t)r * 2 * EE + e];
    int dst = ei[(size_t)r * 2 * EE + EE + e];
    int pos = atomicAdd(&cur[r * NN + dst], 1);
    int2 p;
    p.x = src;
    p.y = __float_as_int(dinv[r * NN + src]);
    pe[pos] = p;
}

// ---------------- weight preconversion (seg0 of cheb folds W0 - W2) ----------------
__global__ void preconv_kernel(const float* __restrict__ chebW,
                               const float* __restrict__ projW,
                               const float* __restrict__ W1,
                               __nv_bfloat16* __restrict__ Bhi,
                               __nv_bfloat16* __restrict__ Blo) {
    int idx = blockIdx.x * blockDim.x + threadIdx.x;
    if (idx >= NCH_TOTAL * 8192) return;
    int c = idx >> 13;
    int e = idx & 8191;
    int n = e >> 6;
    int kk = e & 63;
    const float* src;
    int kloc;
    if (c < 108)      { src = chebW + (size_t)(c / 6) * (KK * HH * HH); kloc = (c % 6) * 64; }
    else if (c < 120) { src = projW; kloc = (c - 108) * 64; }
    else              { src = W1;    kloc = (c - 120) * 64; }
    float v = src[(size_t)(kloc + kk) * HH + n];
    // Chebyshev fold: T2 = 2*P(T1) - h  =>  h coefficient becomes (W0 - W2)
    if (c < 108 && (c % 6) < 2)
        v -= src[(size_t)(kloc + kk + 256) * HH + n];
    __nv_bfloat16 hi = __float2bfloat16(v);
    __nv_bfloat16 lo = __float2bfloat16(v - __bfloat162float(hi));
    uint32_t off = SW128((uint32_t)(n * 128 + kk * 2)) >> 1;
    Bhi[(size_t)c * 8192 + off] = hi;
    Blo[(size_t)c * 8192 + off] = lo;
}

__global__ void xsplit_kernel(const float4* __restrict__ x,
                              __nv_bfloat16* __restrict__ hi, __nv_bfloat16* __restrict__ lo) {
    int t = blockIdx.x * blockDim.x + threadIdx.x;
    if (t >= NN * 32) return;
    int row = t >> 5;
    int lane = t & 31;
    float4 v = x[t];
    int tile = row >> 7;
    int mloc = row & 127;
    int p = lane >> 4;
    int kk = (lane * 4) & 63;
    split_store4(hi, lo, (size_t)(tile * 2 + p) * 16384, mloc, kk, v.x, v.y, v.z, v.w);
}

// ---------------- descriptors ----------------
struct Seg { const __nv_bfloat16* hi[6]; const __nv_bfloat16* lo[6]; };

struct PropBatch {
    const float4* hin[RR];
    float4* hout[RR];
    __nv_bfloat16 *Ohi[RR], *Olo[RR];
    float alpha;
};

struct GemmBatch {
    Seg A[RR];
    const __nv_bfloat16 *Bh[RR], *Bl[RR];
    const float* bias[RR];
    float* C[RR];
    __nv_bfloat16 *Ohi[RR], *Olo[RR];
};

// ---------------- prop body (packed edges: 2 LDG/edge) ----------------
__device__ __forceinline__ void prop_body(const float4* __restrict__ hin,
                                          float4* __restrict__ hout,
                                          const int* __restrict__ rowptr,
                                          const int2* __restrict__ pe,
                                          const float* __restrict__ dinv,
                                          float alpha,
                                          __nv_bfloat16* __restrict__ Ohi,
                                          __nv_bfloat16* __restrict__ Olo, int vb) {
    int t = vb * 256 + threadIdx.x;
    int w = t >> 5;
    int lane = t & 31;
    if (w >= NN) return;
    int e = rowptr[w];
    int e1 = rowptr[w + 1];
    float4 acc = make_float4(0.f, 0.f, 0.f, 0.f);
    for (; e + 3 < e1; e += 4) {
        int2 p0 = __ldg(&pe[e]);
        int2 p1 = __ldg(&pe[e + 1]);
        int2 p2 = __ldg(&pe[e + 2]);
        int2 p3 = __ldg(&pe[e + 3]);
        float w0 = __int_as_float(p0.y);
        float w1 = __int_as_float(p1.y);
        float w2 = __int_as_float(p2.y);
        float w3 = __int_as_float(p3.y);
        float4 v0 = hin[(size_t)p0.x * 32 + lane];
        float4 v1 = hin[(size_t)p1.x * 32 + lane];
        float4 v2 = hin[(size_t)p2.x * 32 + lane];
        float4 v3 = hin[(size_t)p3.x * 32 + lane];
        acc.x += w0 * v0.x + w1 * v1.x + w2 * v2.x + w3 * v3.x;
        acc.y += w0 * v0.y + w1 * v1.y + w2 * v2.y + w3 * v3.y;
        acc.z += w0 * v0.z + w1 * v1.z + w2 * v2.z + w3 * v3.z;
        acc.w += w0 * v0.w + w1 * v1.w + w2 * v2.w + w3 * v3.w;
    }
    for (; e < e1; e++) {
        int2 p0 = __ldg(&pe[e]);
        float w0 = __int_as_float(p0.y);
        float4 v0 = hin[(size_t)p0.x * 32 + lane];
        acc.x += w0 * v0.x;
        acc.y += w0 * v0.y;
        acc.z += w0 * v0.z;
        acc.w += w0 * v0.w;
    }
    float sc = -alpha * dinv[w];
    float4 r;
    r.x = sc * acc.x; r.y = sc * acc.y; r.z = sc * acc.z; r.w = sc * acc.w;
    if (hout) hout[(size_t)w * 32 + lane] = r;
    int tile = w >> 7;
    int mloc = w & 127;
    int p = lane >> 4;
    int kk = (lane * 4) & 63;
    split_store4(Ohi, Olo, (size_t)(tile * 2 + p) * 16384, mloc, kk, r.x, r.y, r.z, r.w);
}

// ---------------- HMMA GEMM body (256 thr, 2 CTA/SM, single buffer) ----------------
__device__ __forceinline__ void gemm_body(const Seg& A, const __nv_bfloat16* __restrict__ Bhi,
                                          const __nv_bfloat16* __restrict__ Blo,
                                          const float* __restrict__ bias, float* __restrict__ C,
                                          __nv_bfloat16* __restrict__ Ohi,
                                          __nv_bfloat16* __restrict__ Olo,
                                          int nchunks, int relu, int vb) {
    extern __shared__ char smem[];
    const uint32_t sb = smem_u32(smem);
    const int tid = threadIdx.x;
    const int wid = tid >> 5;
    const int lane = tid & 31;
    const int bm = vb * 128;
    const int mwarp = (wid >> 2) * 64;
    const int nwarp = (wid & 3) * 32;

    const int sel = lane >> 3;
    const int r8 = lane & 7;
    const int lm_roff = (sel & 1) * 8 + r8;
    const int lm_kbyte = (sel >> 1) * 16;

    float c[4][4][4];
#pragma unroll
    for (int i = 0; i < 4; i++)
#pragma unroll
        for (int j = 0; j < 4; j++)
#pragma unroll
            for (int q = 0; q < 4; q++) c[i][j][q] = 0.f;

    for (int ch = 0; ch < nchunks; ch++) {
        const int seg = ch >> 1, par = ch & 1;
        const char* pAh = (const char*)A.hi[seg] + (size_t)(vb * 2 + par) * 16384;
        const char* pAl = (const char*)A.lo[seg] + (size_t)(vb * 2 + par) * 16384;
        const char* pBh = (const char*)(Bhi + (size_t)ch * 8192);
        const char* pBl = (const char*)(Blo + (size_t)ch * 8192);
#pragma unroll
        for (int it = 0; it < 4; it++) {
            uint32_t q = (uint32_t)(it * 256 + tid) * 16;
            cpa16(sb + q,         pAh + q);
            cpa16(sb + 16384 + q, pAl + q);
            cpa16(sb + 32768 + q, pBh + q);
            cpa16(sb + 49152 + q, pBl + q);
        }
        asm volatile("cp.async.commit_group;");
        asm volatile("cp.async.wait_group 0;");
        __syncthreads();

#pragma unroll
        for (int ks = 0; ks < 4; ks++) {
            const int kb = ks * 32 + lm_kbyte;
            uint32_t afr[16], bfr[8];
#pragma unroll
            for (int g = 0; g < 2; g++)
                ldsm4(bfr + g * 4,
                      sb + 49152 + SW128((uint32_t)((nwarp + g * 16 + lm_roff) * 128 + kb)));
#pragma unroll
            for (int mt = 0; mt < 4; mt++)
                ldsm4(afr + mt * 4,
                      sb + SW128((uint32_t)((mwarp + mt * 16 + lm_roff) * 128 + kb)));
            // Ahi * Blo
#pragma unroll
            for (int mt = 0; mt < 4; mt++)
#pragma unroll
                for (int nt = 0; nt < 4; nt++)
                    mma16816(c[mt][nt], afr + mt * 4,
                             bfr[(nt >> 1) * 4 + (nt & 1)], bfr[(nt >> 1) * 4 + 2 + (nt & 1)]);
#pragma unroll
            for (int g = 0; g < 2; g++)
                ldsm4(bfr + g * 4,
                      sb + 32768 + SW128((uint32_t)((nwarp + g * 16 + lm_roff) * 128 + kb)));
            // Ahi * Bhi
#pragma unroll
            for (int mt = 0; mt < 4; mt++)
#pragma unroll
                for (int nt = 0; nt < 4; nt++)
                    mma16816(c[mt][nt], afr + mt * 4,
                             bfr[(nt >> 1) * 4 + (nt & 1)], bfr[(nt >> 1) * 4 + 2 + (nt & 1)]);
#pragma unroll
            for (int mt = 0; mt < 4; mt++)
                ldsm4(afr + mt * 4,
                      sb + 16384 + SW128((uint32_t)((mwarp + mt * 16 + lm_roff) * 128 + kb)));
            // Alo * Bhi
#pragma unroll
            for (int mt = 0; mt < 4; mt++)
#pragma unroll
                for (int nt = 0; nt < 4; nt++)
                    mma16816(c[mt][nt], afr + mt * 4,
                             bfr[(nt >> 1) * 4 + (nt & 1)], bfr[(nt >> 1) * 4 + 2 + (nt & 1)]);
        }
        __syncthreads();
    }

    const int crow = lane >> 2;
    const int ccol = (lane & 3) * 2;
#pragma unroll
    for (int mt = 0; mt < 4; mt++) {
#pragma unroll
        for (int half = 0; half < 2; half++) {
            int mloc = mwarp + mt * 16 + crow + half * 8;
            int gm = bm + mloc;
            if (gm < NN) {
#pragma unroll
                for (int nt = 0; nt < 4; nt++) {
                    int gn = nwarp + nt * 8 + ccol;
                    float v0 = c[mt][nt][half * 2 + 0] + bias[gn];
                    float v1 = c[mt][nt][half * 2 + 1] + bias[gn + 1];
                    if (relu) { v0 = fmaxf(v0, 0.f); v1 = fmaxf(v1, 0.f); }
                    if (C) {
                        float2 o; o.x = v0; o.y = v1;
                        *(float2*)(C + (size_t)gm * HH + gn) = o;
                    }
                    if (Ohi) {
                        __nv_bfloat162 h2, l2;
                        h2.x = __float2bfloat16(v0);
                        h2.y = __float2bfloat16(v1);
                        l2.x = __float2bfloat16(v0 - __bfloat162float(h2.x));
                        l2.y = __float2bfloat16(v1 - __bfloat162float(h2.y));
                        int p = gn >> 6;
                        int kk = gn & 63;
                        size_t imgB = (size_t)(vb * 2 + p) * 16384;
                        uint32_t off = SW128((uint32_t)(mloc * 128 + kk * 2));
                        *(uint32_t*)((char*)Ohi + imgB + off) = *(uint32_t*)&h2;
                        *(uint32_t*)((char*)Olo + imgB + off) = *(uint32_t*)&l2;
                    }
                }
            }
        }
    }
}

// ---------------- batched kernels ----------------
__global__ void propb_kernel(PropBatch pb, const int* __restrict__ rp,
                             const int2* __restrict__ pe, const float* __restrict__ dinvAll) {
    int r = blockIdx.x / PROP_BLOCKS;
    int vb = blockIdx.x - r * PROP_BLOCKS;
    prop_body(pb.hin[r], pb.hout[r], rp + r * NN, pe, dinvAll + r * NN,
              pb.alpha, pb.Ohi[r], pb.Olo[r], vb);
}

__global__ __launch_bounds__(256, 2)
void gemmb_kernel(GemmBatch gb, int nchunks, int relu) {
    int r = blockIdx.x / NT;
    int vb = blockIdx.x - r * NT;
    gemm_body(gb.A[r], gb.Bh[r], gb.Bl[r], gb.bias[r], gb.C[r],
              gb.Ohi[r], gb.Olo[r], nchunks, relu, vb);
}

__global__ __launch_bounds__(256, 2)
void gemm_mma(Seg A, const __nv_bfloat16* __restrict__ Bhi,
              const __nv_bfloat16* __restrict__ Blo,
              const float* __restrict__ bias, float* __restrict__ C,
              __nv_bfloat16* __restrict__ Ohi, __nv_bfloat16* __restrict__ Olo,
              int nchunks, int relu) {
    gemm_body(A, Bhi, Blo, bias, C, Ohi, Olo, nchunks, relu, blockIdx.x);
}

// ---------------- final: logit + aux ----------------
__global__ void final_kernel(const float4* __restrict__ hc, const float4* __restrict__ emb,
                             const float* __restrict__ clsW2, const float* __restrict__ clsb2,
                             const float* __restrict__ auxW, const float* __restrict__ auxB,
                             float* __restrict__ out) {
    int t = blockIdx.x * blockDim.x + threadIdx.x;
    int gw = t >> 5;
    int lane = t & 31;
    if (gw >= (RR + 1) * NN) return;
    const float4* vec;
    const float4* wv;
    float b;
    if (gw < NN) {
        vec = hc + (size_t)gw * 32;
        wv = (const float4*)clsW2;
        b = clsb2[0];
    } else {
        int r = (gw - NN) / NN;
        int n = (gw - NN) - r * NN;
        vec = emb + ((size_t)r * NN + n) * 32;
        wv = (const float4*)(auxW + r * HH);
        b = auxB[r];
    }
    float4 a = vec[lane];
    float4 w = wv[lane];
    float s = a.x * w.x + a.y * w.y + a.z * w.z + a.w * w.w;
#pragma unroll
    for (int off = 16; off; off >>= 1) s += __shfl_xor_sync(0xFFFFFFFFu, s, off);
    if (lane == 0) out[gw] = s + b;
}

// ---------------- launch ----------------
extern "C" void kernel_launch(void* const* d_in, const int* in_sizes, int n_in,
                              void* d_out, int out_size) {
    (void)in_sizes; (void)n_in; (void)out_size;
    const float* x     = (const float*)d_in[0];
    const int*   ei    = (const int*)d_in[1];
    const float* chebW = (const float*)d_in[2];
    const float* chebB = (const float*)d_in[3];
    const float* projW = (const float*)d_in[4];
    const float* projB = (const float*)d_in[5];
    const float* W1    = (const float*)d_in[6];
    const float* b1    = (const float*)d_in[7];
    const float* W2    = (const float*)d_in[8];
    const float* b2    = (const float*)d_in[9];
    const float* auxW  = (const float*)d_in[10];
    const float* auxB  = (const float*)d_in[11];
    float* out = (float*)d_out;

    float *emb, *txF, *hAf, *hBf, *dinv;
    int *deg, *cnt, *rp, *cur, *bs;
    int2* pe;
    __nv_bfloat16 *Bhi, *Blo, *xsh, *xsl, *rimg, *esh, *esl;
    cudaGetSymbolAddress((void**)&emb, g_emb);
    cudaGetSymbolAddress((void**)&txF, g_txF);
    cudaGetSymbolAddress((void**)&hAf, g_hAf);
    cudaGetSymbolAddress((void**)&hBf, g_hBf);
    cudaGetSymbolAddress((void**)&dinv, g_dinv);
    cudaGetSymbolAddress((void**)&deg, g_deg);
    cudaGetSymbolAddress((void**)&cnt, g_cnt);
    cudaGetSymbolAddress((void**)&rp, g_rp);
    cudaGetSymbolAddress((void**)&cur, g_cur);
    cudaGetSymbolAddress((void**)&pe, g_pe);
    cudaGetSymbolAddress((void**)&bs, g_bsums);
    cudaGetSymbolAddress((void**)&Bhi, g_Bhi);
    cudaGetSymbolAddress((void**)&Blo, g_Blo);
    cudaGetSymbolAddress((void**)&xsh, g_xs_hi);
    cudaGetSymbolAddress((void**)&xsl, g_xs_lo);
    cudaGetSymbolAddress((void**)&rimg, g_rimg);
    cudaGetSymbolAddress((void**)&esh, g_es_hi);
    cudaGetSymbolAddress((void**)&esl, g_es_lo);

    const int SMEM_BYTES = 65536;
    cudaFuncSetAttribute(gemm_mma, cudaFuncAttributeMaxDynamicSharedMemorySize, SMEM_BYTES);
    cudaFuncSetAttribute(gemmb_kernel, cudaFuncAttributeMaxDynamicSharedMemorySize, SMEM_BYTES);

    // ---- serial head ----
    zero2_kernel<<<(RR * NN + 255) / 256, 256>>>(deg, cnt, RR * NN);
    count_kernel<<<(RR * EE + 255) / 256, 256>>>(ei, deg, cnt);
    dinv_kernel<<<(RR * NN + 255) / 256, 256>>>(deg, dinv);
    const int ntot = RR * NN;
    const int nb = (ntot + 1023) / 1024;
    scan1_kernel<<<nb, 1024>>>(cnt, rp, bs, ntot);
    scan2_kernel<<<1, 512>>>(bs, nb);
    scan3_kernel<<<nb, 1024>>>(rp, bs, cur, ntot, RR * EE);
    fill_kernel<<<(RR * EE + 255) / 256, 256>>>(ei, cur, pe, dinv);
    preconv_kernel<<<(NCH_TOTAL * 8192 + 255) / 256, 256>>>(chebW, projW, W1, Bhi, Blo);
    xsplit_kernel<<<(NN * 32 + 255) / 256, 256>>>((const float4*)x, xsh, xsl);

    // ---- per-relation pointer tables ----
    const float* h_fp32[RR][LL];
    const __nv_bfloat16 *h_hi[RR][LL], *h_lo[RR][LL];
    float* g_out[RR][LL];
    __nv_bfloat16 *g_oh[RR][LL], *g_ol[RR][LL];
    __nv_bfloat16 *txh_[RR], *txl_[RR], *tx2h_[RR], *tx2l_[RR];
    float* txr_[RR];
    for (int r = 0; r < RR; r++) {
        __nv_bfloat16* ri = rimg + (size_t)r * 8 * IMG_ELEMS;
        txh_[r] = ri;                  txl_[r] = ri + IMG_ELEMS;
        tx2h_[r] = ri + 2 * IMG_ELEMS; tx2l_[r] = ri + 3 * IMG_ELEMS;
        __nv_bfloat16 *hAh = ri + 4 * IMG_ELEMS, *hAl = ri + 5 * IMG_ELEMS;
        __nv_bfloat16 *hBh = ri + 6 * IMG_ELEMS, *hBl = ri + 7 * IMG_ELEMS;
        txr_[r] = txF + (size_t)r * NHE;
        h_fp32[r][0] = x;  h_hi[r][0] = xsh; h_lo[r][0] = xsl;
        g_out[r][0] = hAf + (size_t)r * NHE; g_oh[r][0] = hAh; g_ol[r][0] = hAl;
        g_out[r][1] = hBf + (size_t)r * NHE; g_oh[r][1] = hBh; g_ol[r][1] = hBl;
        g_out[r][2] = emb + (size_t)r * NHE;
        g_oh[r][2] = esh + (size_t)r * IMG_ELEMS;
        g_ol[r][2] = esl + (size_t)r * IMG_ELEMS;
        for (int l = 1; l < LL; l++) {
            h_fp32[r][l] = g_out[r][l - 1];
            h_hi[r][l] = g_oh[r][l - 1];
            h_lo[r][l] = g_ol[r][l - 1];
        }
    }

    // ---- layer loop: batched across relations ----
    for (int l = 0; l < LL; l++) {
        PropBatch p1;
        p1.alpha = 1.0f;
        for (int r = 0; r < RR; r++) {
            p1.hin[r] = (const float4*)h_fp32[r][l];
            p1.hout[r] = (float4*)txr_[r];
            p1.Ohi[r] = txh_[r]; p1.Olo[r] = txl_[r];
        }
        propb_kernel<<<RR * PROP_BLOCKS, 256>>>(p1, rp, pe, dinv);

        PropBatch p2;
        p2.alpha = 2.0f;   // tx2' = 2*P(tx); the -h term is folded into seg0 weights
        for (int r = 0; r < RR; r++) {
            p2.hin[r] = (const float4*)txr_[r];
            p2.hout[r] = nullptr;
            p2.Ohi[r] = tx2h_[r]; p2.Olo[r] = tx2l_[r];
        }
        propb_kernel<<<RR * PROP_BLOCKS, 256>>>(p2, rp, pe, dinv);

        GemmBatch gb;
        for (int r = 0; r < RR; r++) {
            for (int i = 0; i < 6; i++) { gb.A[r].hi[i] = nullptr; gb.A[r].lo[i] = nullptr; }
            gb.A[r].hi[0] = h_hi[r][l];  gb.A[r].lo[0] = h_lo[r][l];
            gb.A[r].hi[1] = txh_[r];     gb.A[r].lo[1] = txl_[r];
            gb.A[r].hi[2] = tx2h_[r];    gb.A[r].lo[2] = tx2l_[r];
            int g = r * LL + l;
            gb.Bh[r] = Bhi + (size_t)(g * 6) * 8192;
            gb.Bl[r] = Blo + (size_t)(g * 6) * 8192;
            gb.bias[r] = chebB + (size_t)g * HH;
            gb.C[r] = g_out[r][l];
            gb.Ohi[r] = g_oh[r][l];
            gb.Olo[r] = g_ol[r][l];
        }
        gemmb_kernel<<<RR * NT, 256, SMEM_BYTES>>>(gb, 6, 1);
    }

    // ---- serial tail ----
    __nv_bfloat16* ri0 = rimg;   // relation-0 tx images, dead now -> scratch for hp
    Seg sp;
    for (int r = 0; r < RR; r++) {
        sp.hi[r] = esh + (size_t)r * IMG_ELEMS;
        sp.lo[r] = esl + (size_t)r * IMG_ELEMS;
    }
    gemm_mma<<<NT, 256, SMEM_BYTES>>>(sp, Bhi + (size_t)108 * 8192,
        Blo + (size_t)108 * 8192, projB, (float*)nullptr, ri0, ri0 + IMG_ELEMS, 12, 1);

    Seg s1;
    s1.hi[0] = ri0; s1.lo[0] = ri0 + IMG_ELEMS;
    for (int i = 1; i < 6; i++) { s1.hi[i] = nullptr; s1.lo[i] = nullptr; }
    gemm_mma<<<NT, 256, SMEM_BYTES>>>(s1, Bhi + (size_t)120 * 8192,
        Blo + (size_t)120 * 8192, b1, hBf,
        (__nv_bfloat16*)nullptr, (__nv_bfloat16*)nullptr, 2, 1);

    final_kernel<<<((RR + 1) * NN * 32 + 255) / 256, 256>>>(
        (const float4*)hBf, (const float4*)emb, W2, b2, auxW, auxB, out);
}

// round 15
// speedup vs baseline: 1.0077x; 1.0077x over previous
#include <cuda_runtime.h>
#include <cuda_bf16.h>
#include <cstdint>

#define NN 50000
#define HH 128
#define RR 6
#define EE 800000
#define LL 3
#define KK 3

#define NT 391                     // row tiles of 128
#define IMG_ELEMS ((size_t)NT * 2 * 8192)   // bf16 elems per split image (hi or lo)
#define NHE ((size_t)NN * HH)
#define PROP_BLOCKS 6250           // NN*32/256

// total B chunks: 18 cheb GEMMs * 6 + proj 12 + cls1 2 = 122
#define NCH_TOTAL 122

// ---------------- static device scratch ----------------
__device__ __align__(16) static float g_emb[(size_t)RR * NHE];
__device__ __align__(16) static float g_txF[(size_t)RR * NHE];
__device__ __align__(16) static float g_hAf[(size_t)RR * NHE];
__device__ __align__(16) static float g_hBf[(size_t)RR * NHE];
__device__ static int   g_deg[RR * NN];
__device__ static int   g_cnt[RR * NN];
__device__ static int   g_rp[RR * NN + 1];
__device__ static int   g_cur[RR * NN];
__device__ __align__(16) static int2 g_pe[(size_t)RR * EE];   // packed {src, dinv[src]}
__device__ static float g_dinv[RR * NN];
__device__ static int   g_bsums[1024];
__device__ __align__(16) static __nv_bfloat16 g_Bhi[(size_t)NCH_TOTAL * 8192];
__device__ __align__(16) static __nv_bfloat16 g_Blo[(size_t)NCH_TOTAL * 8192];
__device__ __align__(16) static __nv_bfloat16 g_xs_hi[IMG_ELEMS], g_xs_lo[IMG_ELEMS];
// per-relation split images: [rel][buf: 0 txh,1 txl,2 tx2h,3 tx2l,4 hAh,5 hAl,6 hBh,7 hBl]
__device__ __align__(16) static __nv_bfloat16 g_rimg[(size_t)RR * 8 * IMG_ELEMS];
__device__ __align__(16) static __nv_bfloat16 g_es_hi[(size_t)RR * IMG_ELEMS];
__device__ __align__(16) static __nv_bfloat16 g_es_lo[(size_t)RR * IMG_ELEMS];

#define SW128(off) ((off) ^ (((off) >> 3) & 0x70))

__device__ __forceinline__ uint32_t smem_u32(const void* p) {
    uint32_t a;
    asm("{ .reg .u64 t; cvta.to.shared.u64 t, %1; cvt.u32.u64 %0, t; }" : "=r"(a) : "l"(p));
    return a;
}
__device__ __forceinline__ void ldsm4(uint32_t* r, uint32_t addr) {
    asm volatile("ldmatrix.sync.aligned.m8n8.x4.shared.b16 {%0,%1,%2,%3}, [%4];"
                 : "=r"(r[0]), "=r"(r[1]), "=r"(r[2]), "=r"(r[3]) : "r"(addr));
}
__device__ __forceinline__ void mma16816(float* c, const uint32_t* a, uint32_t b0, uint32_t b1) {
    asm volatile("mma.sync.aligned.m16n8k16.row.col.f32.bf16.bf16.f32 "
                 "{%0,%1,%2,%3}, {%4,%5,%6,%7}, {%8,%9}, {%0,%1,%2,%3};"
                 : "+f"(c[0]), "+f"(c[1]), "+f"(c[2]), "+f"(c[3])
                 : "r"(a[0]), "r"(a[1]), "r"(a[2]), "r"(a[3]), "r"(b0), "r"(b1));
}
__device__ __forceinline__ void cpa16(uint32_t s, const void* g) {
    asm volatile("cp.async.cg.shared.global [%0], [%1], 16;" :: "r"(s), "l"(g));
}

__device__ __forceinline__ void split_store4(__nv_bfloat16* hi, __nv_bfloat16* lo,
                                             size_t imgByte, int mloc, int kk,
                                             float vx, float vy, float vz, float vw) {
    __nv_bfloat162 h0, h1, l0, l1;
    h0.x = __float2bfloat16(vx); h0.y = __float2bfloat16(vy);
    h1.x = __float2bfloat16(vz); h1.y = __float2bfloat16(vw);
    l0.x = __float2bfloat16(vx - __bfloat162float(h0.x));
    l0.y = __float2bfloat16(vy - __bfloat162float(h0.y));
    l1.x = __float2bfloat16(vz - __bfloat162float(h1.x));
    l1.y = __float2bfloat16(vw - __bfloat162float(h1.y));
    uint32_t off = SW128((uint32_t)(mloc * 128 + kk * 2));
    uint2 hv, lv;
    hv.x = *(uint32_t*)&h0; hv.y = *(uint32_t*)&h1;
    lv.x = *(uint32_t*)&l0; lv.y = *(uint32_t*)&l1;
    *(uint2*)((char*)hi + imgByte + off) = hv;
    *(uint2*)((char*)lo + imgByte + off) = lv;
}

// ---------------- CSR build ----------------
__global__ void zero2_kernel(int* a, int* b, int n) {
    int i = blockIdx.x * blockDim.x + threadIdx.x;
    if (i < n) { a[i] = 0; b[i] = 0; }
}
__global__ void count_kernel(const int* __restrict__ ei, int* __restrict__ deg,
                             int* __restrict__ cnt) {
    int idx = blockIdx.x * blockDim.x + threadIdx.x;
    if (idx >= RR * EE) return;
    int r = idx / EE;
    int e = idx - r * EE;
    int src = ei[(size_t)r * 2 * EE + e];
    int dst = ei[(size_t)r * 2 * EE + EE + e];
    atomicAdd(&deg[r * NN + src], 1);
    atomicAdd(&cnt[r * NN + dst], 1);
}
__global__ void dinv_kernel(const int* __restrict__ deg, float* __restrict__ dinv) {
    int i = blockIdx.x * blockDim.x + threadIdx.x;
    if (i >= RR * NN) return;
    int d = deg[i];
    dinv[i] = (d > 0) ? rsqrtf((float)d) : 0.0f;
}
__global__ void scan1_kernel(const int* __restrict__ in, int* __restrict__ out,
                             int* __restrict__ bsums, int n) {
    __shared__ int sh[1024];
    int i = blockIdx.x * 1024 + threadIdx.x;
    int v = (i < n) ? in[i] : 0;
    sh[threadIdx.x] = v;
    __syncthreads();
    for (int off = 1; off < 1024; off <<= 1) {
        int t = (threadIdx.x >= off) ? sh[threadIdx.x - off] : 0;
        __syncthreads();
        sh[threadIdx.x] += t;
        __syncthreads();
    }
    if (i < n) out[i] = sh[threadIdx.x] - v;
    if (threadIdx.x == 1023) bsums[blockIdx.x] = sh[1023];
}
__global__ void scan2_kernel(int* bsums, int nb) {
    __shared__ int sh[512];
    int v = (threadIdx.x < nb) ? bsums[threadIdx.x] : 0;
    sh[threadIdx.x] = v;
    __syncthreads();
    for (int off = 1; off < 512; off <<= 1) {
        int t = (threadIdx.x >= off) ? sh[threadIdx.x - off] : 0;
        __syncthreads();
        sh[threadIdx.x] += t;
        __syncthreads();
    }
    if (threadIdx.x < nb) bsums[threadIdx.x] = sh[threadIdx.x] - v;
}
__global__ void scan3_kernel(int* __restrict__ rp, const int* __restrict__ bsums,
                             int* __restrict__ cur, int n, int total) {
    int i = blockIdx.x * 1024 + threadIdx.x;
    if (i < n) {
        int v = rp[i] + bsums[blockIdx.x];
        rp[i] = v;
        cur[i] = v;
    }
    if (i == 0) rp[n] = total;
}
// fill packed edges: {src, dinv[src]} sorted by dst (CSR order)
__global__ void fill_kernel(const int* __restrict__ ei, int* __restrict__ cur,
                            int2* __restrict__ pe, const float* __restrict__ dinv) {
    int idx = blockIdx.x * blockDim.x + threadIdx.x;
    if (idx >= RR * EE) return;
    int r = idx / EE;
    int e = idx - r * EE;
    int src = ei[(size_t)r * 2 * EE + e];
    int dst = ei[(size_t)r * 2 * EE + EE + e];
    int pos = atomicAdd(&cur[r * NN + dst], 1);
    int2 p;
    p.x = src;
    p.y = __float_as_int(dinv[r * NN + src]);
    pe[pos] = p;
}

// ---------------- weight preconversion (seg0 of cheb folds W0 - W2) ----------------
__global__ void preconv_kernel(const float* __restrict__ chebW,
                               const float* __restrict__ projW,
                               const float* __restrict__ W1,
                               __nv_bfloat16* __restrict__ Bhi,
                               __nv_bfloat16* __restrict__ Blo) {
    int idx = blockIdx.x * blockDim.x + threadIdx.x;
    if (idx >= NCH_TOTAL * 8192) return;
    int c = idx >> 13;
    int e = idx & 8191;
    int n = e >> 6;
    int kk = e & 63;
    const float* src;
    int kloc;
    if (c < 108)      { src = chebW + (size_t)(c / 6) * (KK * HH * HH); kloc = (c % 6) * 64; }
    else if (c < 120) { src = projW; kloc = (c - 108) * 64; }
    else              { src = W1;    kloc = (c - 120) * 64; }
    float v = src[(size_t)(kloc + kk) * HH + n];
    // Chebyshev fold: T2 = 2*P(T1) - h  =>  h coefficient becomes (W0 - W2)
    if (c < 108 && (c % 6) < 2)
        v -= src[(size_t)(kloc + kk + 256) * HH + n];
    __nv_bfloat16 hi = __float2bfloat16(v);
    __nv_bfloat16 lo = __float2bfloat16(v - __bfloat162float(hi));
    uint32_t off = SW128((uint32_t)(n * 128 + kk * 2)) >> 1;
    Bhi[(size_t)c * 8192 + off] = hi;
    Blo[(size_t)c * 8192 + off] = lo;
}

__global__ void xsplit_kernel(const float4* __restrict__ x,
                              __nv_bfloat16* __restrict__ hi, __nv_bfloat16* __restrict__ lo) {
    int t = blockIdx.x * blockDim.x + threadIdx.x;
    if (t >= NN * 32) return;
    int row = t >> 5;
    int lane = t & 31;
    float4 v = x[t];
    int tile = row >> 7;
    int mloc = row & 127;
    int p = lane >> 4;
    int kk = (lane * 4) & 63;
    split_store4(hi, lo, (size_t)(tile * 2 + p) * 16384, mloc, kk, v.x, v.y, v.z, v.w);
}

// ---------------- descriptors ----------------
struct Seg { const __nv_bfloat16* hi[6]; const __nv_bfloat16* lo[6]; };

struct PropBatch {
    const float4* hin[RR];
    float4* hout[RR];
    __nv_bfloat16 *Ohi[RR], *Olo[RR];
    float alpha;
};

struct GemmBatch {
    Seg A[RR];
    const __nv_bfloat16 *Bh[RR], *Bl[RR];
    const float* bias[RR];
    float* C[RR];
    __nv_bfloat16 *Ohi[RR], *Olo[RR];
};

// ---------------- prop body (packed edges: 2 LDG/edge) ----------------
__device__ __forceinline__ void prop_body(const float4* __restrict__ hin,
                                          float4* __restrict__ hout,
                                          const int* __restrict__ rowptr,
                                          const int2* __restrict__ pe,
                                          const float* __restrict__ dinv,
                                          float alpha,
                                          __nv_bfloat16* __restrict__ Ohi,
                                          __nv_bfloat16* __restrict__ Olo, int vb) {
    int t = vb * 256 + threadIdx.x;
    int w = t >> 5;
    int lane = t & 31;
    if (w >= NN) return;
    int e = rowptr[w];
    int e1 = rowptr[w + 1];
    float4 acc = make_float4(0.f, 0.f, 0.f, 0.f);
    for (; e + 3 < e1; e += 4) {
        int2 p0 = __ldg(&pe[e]);
        int2 p1 = __ldg(&pe[e + 1]);
        int2 p2 = __ldg(&pe[e + 2]);
        int2 p3 = __ldg(&pe[e + 3]);
        float w0 = __int_as_float(p0.y);
        float w1 = __int_as_float(p1.y);
        float w2 = __int_as_float(p2.y);
        float w3 = __int_as_float(p3.y);
        float4 v0 = hin[(size_t)p0.x * 32 + lane];
        float4 v1 = hin[(size_t)p1.x * 32 + lane];
        float4 v2 = hin[(size_t)p2.x * 32 + lane];
        float4 v3 = hin[(size_t)p3.x * 32 + lane];
        acc.x += w0 * v0.x + w1 * v1.x + w2 * v2.x + w3 * v3.x;
        acc.y += w0 * v0.y + w1 * v1.y + w2 * v2.y + w3 * v3.y;
        acc.z += w0 * v0.z + w1 * v1.z + w2 * v2.z + w3 * v3.z;
        acc.w += w0 * v0.w + w1 * v1.w + w2 * v2.w + w3 * v3.w;
    }
    for (; e < e1; e++) {
        int2 p0 = __ldg(&pe[e]);
        float w0 = __int_as_float(p0.y);
        float4 v0 = hin[(size_t)p0.x * 32 + lane];
        acc.x += w0 * v0.x;
        acc.y += w0 * v0.y;
        acc.z += w0 * v0.z;
        acc.w += w0 * v0.w;
    }
    float sc = -alpha * dinv[w];
    float4 r;
    r.x = sc * acc.x; r.y = sc * acc.y; r.z = sc * acc.z; r.w = sc * acc.w;
    if (hout) hout[(size_t)w * 32 + lane] = r;
    int tile = w >> 7;
    int mloc = w & 127;
    int p = lane >> 4;
    int kk = (lane * 4) & 63;
    split_store4(Ohi, Olo, (size_t)(tile * 2 + p) * 16384, mloc, kk, r.x, r.y, r.z, r.w);
}

// ---------------- HMMA GEMM body (256 thr, 2 CTA/SM, single buffer) ----------------
__device__ __forceinline__ void gemm_body(const Seg& A, const __nv_bfloat16* __restrict__ Bhi,
                                          const __nv_bfloat16* __restrict__ Blo,
                                          const float* __restrict__ bias, float* __restrict__ C,
                                          __nv_bfloat16* __restrict__ Ohi,
                                          __nv_bfloat16* __restrict__ Olo,
                                          int nchunks, int relu, int vb) {
    extern __shared__ char smem[];
    const uint32_t sb = smem_u32(smem);
    const int tid = threadIdx.x;
    const int wid = tid >> 5;
    const int lane = tid & 31;
    const int bm = vb * 128;
    const int mwarp = (wid >> 2) * 64;
    const int nwarp = (wid & 3) * 32;

    const int sel = lane >> 3;
    const int r8 = lane & 7;
    const int lm_roff = (sel & 1) * 8 + r8;
    const int lm_kbyte = (sel >> 1) * 16;

    float c[4][4][4];
#pragma unroll
    for (int i = 0; i < 4; i++)
#pragma unroll
        for (int j = 0; j < 4; j++)
#pragma unroll
            for (int q = 0; q < 4; q++) c[i][j][q] = 0.f;

    for (int ch = 0; ch < nchunks; ch++) {
        const int seg = ch >> 1, par = ch & 1;
        const char* pAh = (const char*)A.hi[seg] + (size_t)(vb * 2 + par) * 16384;
        const char* pAl = (const char*)A.lo[seg] + (size_t)(vb * 2 + par) * 16384;
        const char* pBh = (const char*)(Bhi + (size_t)ch * 8192);
        const char* pBl = (const char*)(Blo + (size_t)ch * 8192);
#pragma unroll
        for (int it = 0; it < 4; it++) {
            uint32_t q = (uint32_t)(it * 256 + tid) * 16;
            cpa16(sb + q,         pAh + q);
            cpa16(sb + 16384 + q, pAl + q);
            cpa16(sb + 32768 + q, pBh + q);
            cpa16(sb + 49152 + q, pBl + q);
        }
        asm volatile("cp.async.commit_group;");
        asm volatile("cp.async.wait_group 0;");
        __syncthreads();

#pragma unroll
        for (int ks = 0; ks < 4; ks++) {
            const int kb = ks * 32 + lm_kbyte;
            uint32_t afr[16], bfr[8];
#pragma unroll
            for (int g = 0; g < 2; g++)
                ldsm4(bfr + g * 4,
                      sb + 49152 + SW128((uint32_t)((nwarp + g * 16 + lm_roff) * 128 + kb)));
#pragma unroll
            for (int mt = 0; mt < 4; mt++)
                ldsm4(afr + mt * 4,
                      sb + SW128((uint32_t)((mwarp + mt * 16 + lm_roff) * 128 + kb)));
            // Ahi * Blo
#pragma unroll
            for (int mt = 0; mt < 4; mt++)
#pragma unroll
                for (int nt = 0; nt < 4; nt++)
                    mma16816(c[mt][nt], afr + mt * 4,
                             bfr[(nt >> 1) * 4 + (nt & 1)], bfr[(nt >> 1) * 4 + 2 + (nt & 1)]);
#pragma unroll
            for (int g = 0; g < 2; g++)
                ldsm4(bfr + g * 4,
                      sb + 32768 + SW128((uint32_t)((nwarp + g * 16 + lm_roff) * 128 + kb)));
            // Ahi * Bhi
#pragma unroll
            for (int mt = 0; mt < 4; mt++)
#pragma unroll
                for (int nt = 0; nt < 4; nt++)
                    mma16816(c[mt][nt], afr + mt * 4,
                             bfr[(nt >> 1) * 4 + (nt & 1)], bfr[(nt >> 1) * 4 + 2 + (nt & 1)]);
#pragma unroll
            for (int mt = 0; mt < 4; mt++)
                ldsm4(afr + mt * 4,
                      sb + 16384 + SW128((uint32_t)((mwarp + mt * 16 + lm_roff) * 128 + kb)));
            // Alo * Bhi
#pragma unroll
            for (int mt = 0; mt < 4; mt++)
#pragma unroll
                for (int nt = 0; nt < 4; nt++)
                    mma16816(c[mt][nt], afr + mt * 4,
                             bfr[(nt >> 1) * 4 + (nt & 1)], bfr[(nt >> 1) * 4 + 2 + (nt & 1)]);
        }
        __syncthreads();
    }

    const int crow = lane >> 2;
    const int ccol = (lane & 3) * 2;
#pragma unroll
    for (int mt = 0; mt < 4; mt++) {
#pragma unroll
        for (int half = 0; half < 2; half++) {
            int mloc = mwarp + mt * 16 + crow + half * 8;
            int gm = bm + mloc;
            if (gm < NN) {
#pragma unroll
                for (int nt = 0; nt < 4; nt++) {
                    int gn = nwarp + nt * 8 + ccol;
                    float v0 = c[mt][nt][half * 2 + 0] + bias[gn];
                    float v1 = c[mt][nt][half * 2 + 1] + bias[gn + 1];
                    if (relu) { v0 = fmaxf(v0, 0.f); v1 = fmaxf(v1, 0.f); }
                    if (C) {
                        float2 o; o.x = v0; o.y = v1;
                        *(float2*)(C + (size_t)gm * HH + gn) = o;
                    }
                    if (Ohi) {
                        __nv_bfloat162 h2, l2;
                        h2.x = __float2bfloat16(v0);
                        h2.y = __float2bfloat16(v1);
                        l2.x = __float2bfloat16(v0 - __bfloat162float(h2.x));
                        l2.y = __float2bfloat16(v1 - __bfloat162float(h2.y));
                        int p = gn >> 6;
                        int kk = gn & 63;
                        size_t imgB = (size_t)(vb * 2 + p) * 16384;
                        uint32_t off = SW128((uint32_t)(mloc * 128 + kk * 2));
                        *(uint32_t*)((char*)Ohi + imgB + off) = *(uint32_t*)&h2;
                        *(uint32_t*)((char*)Olo + imgB + off) = *(uint32_t*)&l2;
                    }
                }
            }
        }
    }
}

// ---------------- batched kernels ----------------
__global__ void propb_kernel(PropBatch pb, const int* __restrict__ rp,
                             const int2* __restrict__ pe, const float* __restrict__ dinvAll) {
    int r = blockIdx.x / PROP_BLOCKS;
    int vb = blockIdx.x - r * PROP_BLOCKS;
    prop_body(pb.hin[r], pb.hout[r], rp + r * NN, pe, dinvAll + r * NN,
              pb.alpha, pb.Ohi[r], pb.Olo[r], vb);
}

__global__ __launch_bounds__(256, 2)
void gemmb_kernel(GemmBatch gb, int nchunks, int relu) {
    int r = blockIdx.x / NT;
    int vb = blockIdx.x - r * NT;
    gemm_body(gb.A[r], gb.Bh[r], gb.Bl[r], gb.bias[r], gb.C[r],
              gb.Ohi[r], gb.Olo[r], nchunks, relu, vb);
}

__global__ __launch_bounds__(256, 2)
void gemm_mma(Seg A, const __nv_bfloat16* __restrict__ Bhi,
              const __nv_bfloat16* __restrict__ Blo,
              const float* __restrict__ bias, float* __restrict__ C,
              __nv_bfloat16* __restrict__ Ohi, __nv_bfloat16* __restrict__ Olo,
              int nchunks, int relu) {
    gemm_body(A, Bhi, Blo, bias, C, Ohi, Olo, nchunks, relu, blockIdx.x);
}

// ---------------- final: logit + aux ----------------
__global__ void final_kernel(const float4* __restrict__ hc, const float4* __restrict__ emb,
                             const float* __restrict__ clsW2, const float* __restrict__ clsb2,
                             const float* __restrict__ auxW, const float* __restrict__ auxB,
                             float* __restrict__ out) {
    int t = blockIdx.x * blockDim.x + threadIdx.x;
    int gw = t >> 5;
    int lane = t & 31;
    if (gw >= (RR + 1) * NN) return;
    const float4* vec;
    const float4* wv;
    float b;
    if (gw < NN) {
        vec = hc + (size_t)gw * 32;
        wv = (const float4*)clsW2;
        b = clsb2[0];
    } else {
        int r = (gw - NN) / NN;
        int n = (gw - NN) - r * NN;
        vec = emb + ((size_t)r * NN + n) * 32;
        wv = (const float4*)(auxW + r * HH);
        b = auxB[r];
    }
    float4 a = vec[lane];
    float4 w = wv[lane];
    float s = a.x * w.x + a.y * w.y + a.z * w.z + a.w * w.w;
#pragma unroll
    for (int off = 16; off; off >>= 1) s += __shfl_xor_sync(0xFFFFFFFFu, s, off);
    if (lane == 0) out[gw] = s + b;
}

// ---------------- launch ----------------
extern "C" void kernel_launch(void* const* d_in, const int* in_sizes, int n_in,
                              void* d_out, int out_size) {
    (void)in_sizes; (void)n_in; (void)out_size;
    const float* x     = (const float*)d_in[0];
    const int*   ei    = (const int*)d_in[1];
    const float* chebW = (const float*)d_in[2];
    const float* chebB = (const float*)d_in[3];
    const float* projW = (const float*)d_in[4];
    const float* projB = (const float*)d_in[5];
    const float* W1    = (const float*)d_in[6];
    const float* b1    = (const float*)d_in[7];
    const float* W2    = (const float*)d_in[8];
    const float* b2    = (const float*)d_in[9];
    const float* auxW  = (const float*)d_in[10];
    const float* auxB  = (const float*)d_in[11];
    float* out = (float*)d_out;

    float *emb, *txF, *hAf, *hBf, *dinv;
    int *deg, *cnt, *rp, *cur, *bs;
    int2* pe;
    __nv_bfloat16 *Bhi, *Blo, *xsh, *xsl, *rimg, *esh, *esl;
    cudaGetSymbolAddress((void**)&emb, g_emb);
    cudaGetSymbolAddress((void**)&txF, g_txF);
    cudaGetSymbolAddress((void**)&hAf, g_hAf);
    cudaGetSymbolAddress((void**)&hBf, g_hBf);
    cudaGetSymbolAddress((void**)&dinv, g_dinv);
    cudaGetSymbolAddress((void**)&deg, g_deg);
    cudaGetSymbolAddress((void**)&cnt, g_cnt);
    cudaGetSymbolAddress((void**)&rp, g_rp);
    cudaGetSymbolAddress((void**)&cur, g_cur);
    cudaGetSymbolAddress((void**)&pe, g_pe);
    cudaGetSymbolAddress((void**)&bs, g_bsums);
    cudaGetSymbolAddress((void**)&Bhi, g_Bhi);
    cudaGetSymbolAddress((void**)&Blo, g_Blo);
    cudaGetSymbolAddress((void**)&xsh, g_xs_hi);
    cudaGetSymbolAddress((void**)&xsl, g_xs_lo);
    cudaGetSymbolAddress((void**)&rimg, g_rimg);
    cudaGetSymbolAddress((void**)&esh, g_es_hi);
    cudaGetSymbolAddress((void**)&esl, g_es_lo);

    const int SMEM_BYTES = 65536;
    cudaFuncSetAttribute(gemm_mma, cudaFuncAttributeMaxDynamicSharedMemorySize, SMEM_BYTES);
    cudaFuncSetAttribute(gemmb_kernel, cudaFuncAttributeMaxDynamicSharedMemorySize, SMEM_BYTES);

    // ---- serial head ----
    zero2_kernel<<<(RR * NN + 255) / 256, 256>>>(deg, cnt, RR * NN);
    count_kernel<<<(RR * EE + 255) / 256, 256>>>(ei, deg, cnt);
    dinv_kernel<<<(RR * NN + 255) / 256, 256>>>(deg, dinv);
    const int ntot = RR * NN;
    const int nb = (ntot + 1023) / 1024;
    scan1_kernel<<<nb, 1024>>>(cnt, rp, bs, ntot);
    scan2_kernel<<<1, 512>>>(bs, nb);
    scan3_kernel<<<nb, 1024>>>(rp, bs, cur, ntot, RR * EE);
    fill_kernel<<<(RR * EE + 255) / 256, 256>>>(ei, cur, pe, dinv);
    preconv_kernel<<<(NCH_TOTAL * 8192 + 255) / 256, 256>>>(chebW, projW, W1, Bhi, Blo);
    xsplit_kernel<<<(NN * 32 + 255) / 256, 256>>>((const float4*)x, xsh, xsl);

    // ---- per-relation pointer tables ----
    const float* h_fp32[RR][LL];
    const __nv_bfloat16 *h_hi[RR][LL], *h_lo[RR][LL];
    float* g_out[RR][LL];
    __nv_bfloat16 *g_oh[RR][LL], *g_ol[RR][LL];
    __nv_bfloat16 *txh_[RR], *txl_[RR], *tx2h_[RR], *tx2l_[RR];
    float* txr_[RR];
    for (int r = 0; r < RR; r++) {
        __nv_bfloat16* ri = rimg + (size_t)r * 8 * IMG_ELEMS;
        txh_[r] = ri;                  txl_[r] = ri + IMG_ELEMS;
        tx2h_[r] = ri + 2 * IMG_ELEMS; tx2l_[r] = ri + 3 * IMG_ELEMS;
        __nv_bfloat16 *hAh = ri + 4 * IMG_ELEMS, *hAl = ri + 5 * IMG_ELEMS;
        __nv_bfloat16 *hBh = ri + 6 * IMG_ELEMS, *hBl = ri + 7 * IMG_ELEMS;
        txr_[r] = txF + (size_t)r * NHE;
        h_fp32[r][0] = x;  h_hi[r][0] = xsh; h_lo[r][0] = xsl;
        g_out[r][0] = hAf + (size_t)r * NHE; g_oh[r][0] = hAh; g_ol[r][0] = hAl;
        g_out[r][1] = hBf + (size_t)r * NHE; g_oh[r][1] = hBh; g_ol[r][1] = hBl;
        g_out[r][2] = emb + (size_t)r * NHE;
        g_oh[r][2] = esh + (size_t)r * IMG_ELEMS;
        g_ol[r][2] = esl + (size_t)r * IMG_ELEMS;
        for (int l = 1; l < LL; l++) {
            h_fp32[r][l] = g_out[r][l - 1];
            h_hi[r][l] = g_oh[r][l - 1];
            h_lo[r][l] = g_ol[r][l - 1];
        }
    }

    // ---- layer loop: batched across relations ----
    for (int l = 0; l < LL; l++) {
        PropBatch p1;
        p1.alpha = 1.0f;
        for (int r = 0; r < RR; r++) {
            p1.hin[r] = (const float4*)h_fp32[r][l];
            p1.hout[r] = (float4*)txr_[r];
            p1.Ohi[r] = txh_[r]; p1.Olo[r] = txl_[r];
        }
        propb_kernel<<<RR * PROP_BLOCKS, 256>>>(p1, rp, pe, dinv);

        PropBatch p2;
        p2.alpha = 2.0f;   // tx2' = 2*P(tx); the -h term is folded into seg0 weights
        for (int r = 0; r < RR; r++) {
            p2.hin[r] = (const float4*)txr_[r];
            p2.hout[r] = nullptr;
            p2.Ohi[r] = tx2h_[r]; p2.Olo[r] = tx2l_[r];
        }
        propb_kernel<<<RR * PROP_BLOCKS, 256>>>(p2, rp, pe, dinv);

        GemmBatch gb;
        for (int r = 0; r < RR; r++) {
            for (int i = 0; i < 6; i++) { gb.A[r].hi[i] = nullptr; gb.A[r].lo[i] = nullptr; }
            gb.A[r].hi[0] = h_hi[r][l];  gb.A[r].lo[0] = h_lo[r][l];
            gb.A[r].hi[1] = txh_[r];     gb.A[r].lo[1] = txl_[r];
            gb.A[r].hi[2] = tx2h_[r];    gb.A[r].lo[2] = tx2l_[r];
            int g = r * LL + l;
            gb.Bh[r] = Bhi + (size_t)(g * 6) * 8192;
            gb.Bl[r] = Blo + (size_t)(g * 6) * 8192;
            gb.bias[r] = chebB + (size_t)g * HH;
            gb.C[r] = g_out[r][l];
            gb.Ohi[r] = g_oh[r][l];
            gb.Olo[r] = g_ol[r][l];
        }
        gemmb_kernel<<<RR * NT, 256, SMEM_BYTES>>>(gb, 6, 1);
    }

    // ---- serial tail ----
    __nv_bfloat16* ri0 = rimg;   // relation-0 tx images, dead now -> scratch for hp
    Seg sp;
    for (int r = 0; r < RR; r++) {
        sp.hi[r] = esh + (size_t)r * IMG_ELEMS;
        sp.lo[r] = esl + (size_t)r * IMG_ELEMS;
    }
    gemm_mma<<<NT, 256, SMEM_BYTES>>>(sp, Bhi + (size_t)108 * 8192,
        Blo + (size_t)108 * 8192, projB, (float*)nullptr, ri0, ri0 + IMG_ELEMS, 12, 1);

    Seg s1;
    s1.hi[0] = ri0; s1.lo[0] = ri0 + IMG_ELEMS;
    for (int i = 1; i < 6; i++) { s1.hi[i] = nullptr; s1.lo[i] = nullptr; }
    gemm_mma<<<NT, 256, SMEM_BYTES>>>(s1, Bhi + (size_t)120 * 8192,
        Blo + (size_t)120 * 8192, b1, hBf,
        (__nv_bfloat16*)nullptr, (__nv_bfloat16*)nullptr, 2, 1);

    final_kernel<<<((RR + 1) * NN * 32 + 255) / 256, 256>>>(
        (const float4*)hBf, (const float4*)emb, W2, b2, auxW, auxB, out);
}

// round 17
// speedup vs baseline: 1.1828x; 1.1737x over previous
#include <cuda_runtime.h>
#include <cuda_bf16.h>
#include <cstdint>

#define NN 50000
#define HH 128
#define RR 6
#define EE 800000
#define LL 3
#define KK 3

#define NT 391                     // row tiles of 128
#define IMG_ELEMS ((size_t)NT * 2 * 8192)   // bf16 elems per split image (hi or lo)
#define NHE ((size_t)NN * HH)
#define PROP_BLOCKS 6250           // NN*32/256

// total B chunks: 18 cheb GEMMs * 6 + proj 12 + cls1 2 = 122
#define NCH_TOTAL 122

// ---------------- static device scratch ----------------
__device__ __align__(16) static float g_txF[(size_t)RR * NHE];
__device__ __align__(16) static float g_hAf[(size_t)RR * NHE];
__device__ __align__(16) static float g_hBf[(size_t)RR * NHE];
__device__ static int   g_deg[RR * NN];
__device__ static int   g_cnt[RR * NN];
__device__ static int   g_rp[RR * NN + 1];
__device__ static int   g_cur[RR * NN];
__device__ static int   g_col[RR * EE];
__device__ static float g_dinv[RR * NN];
__device__ static int   g_bsums[1024];
__device__ __align__(16) static __nv_bfloat16 g_Bhi[(size_t)NCH_TOTAL * 8192];
__device__ __align__(16) static __nv_bfloat16 g_Blo[(size_t)NCH_TOTAL * 8192];
__device__ __align__(16) static __nv_bfloat16 g_xs_hi[IMG_ELEMS], g_xs_lo[IMG_ELEMS];
// per-relation split images: [rel][buf: 0 txh,1 txl,2 tx2h,3 tx2l,4 hAh,5 hAl,6 hBh,7 hBl]
__device__ __align__(16) static __nv_bfloat16 g_rimg[(size_t)RR * 8 * IMG_ELEMS];
__device__ __align__(16) static __nv_bfloat16 g_es_hi[(size_t)RR * IMG_ELEMS];
__device__ __align__(16) static __nv_bfloat16 g_es_lo[(size_t)RR * IMG_ELEMS];

#define SW128(off) ((off) ^ (((off) >> 3) & 0x70))

__device__ __forceinline__ uint32_t smem_u32(const void* p) {
    uint32_t a;
    asm("{ .reg .u64 t; cvta.to.shared.u64 t, %1; cvt.u32.u64 %0, t; }" : "=r"(a) : "l"(p));
    return a;
}
__device__ __forceinline__ void ldsm4(uint32_t* r, uint32_t addr) {
    asm volatile("ldmatrix.sync.aligned.m8n8.x4.shared.b16 {%0,%1,%2,%3}, [%4];"
                 : "=r"(r[0]), "=r"(r[1]), "=r"(r[2]), "=r"(r[3]) : "r"(addr));
}
__device__ __forceinline__ void mma16816(float* c, const uint32_t* a, uint32_t b0, uint32_t b1) {
    asm volatile("mma.sync.aligned.m16n8k16.row.col.f32.bf16.bf16.f32 "
                 "{%0,%1,%2,%3}, {%4,%5,%6,%7}, {%8,%9}, {%0,%1,%2,%3};"
                 : "+f"(c[0]), "+f"(c[1]), "+f"(c[2]), "+f"(c[3])
                 : "r"(a[0]), "r"(a[1]), "r"(a[2]), "r"(a[3]), "r"(b0), "r"(b1));
}
__device__ __forceinline__ void cpa16(uint32_t s, const void* g) {
    asm volatile("cp.async.cg.shared.global [%0], [%1], 16;" :: "r"(s), "l"(g));
}

__device__ __forceinline__ void split_store4(__nv_bfloat16* hi, __nv_bfloat16* lo,
                                             size_t imgByte, int mloc, int kk,
                                             float vx, float vy, float vz, float vw) {
    __nv_bfloat162 h0, h1, l0, l1;
    h0.x = __float2bfloat16(vx); h0.y = __float2bfloat16(vy);
    h1.x = __float2bfloat16(vz); h1.y = __float2bfloat16(vw);
    l0.x = __float2bfloat16(vx - __bfloat162float(h0.x));
    l0.y = __float2bfloat16(vy - __bfloat162float(h0.y));
    l1.x = __float2bfloat16(vz - __bfloat162float(h1.x));
    l1.y = __float2bfloat16(vw - __bfloat162float(h1.y));
    uint32_t off = SW128((uint32_t)(mloc * 128 + kk * 2));
    uint2 hv, lv;
    hv.x = *(uint32_t*)&h0; hv.y = *(uint32_t*)&h1;
    lv.x = *(uint32_t*)&l0; lv.y = *(uint32_t*)&l1;
    *(uint2*)((char*)hi + imgByte + off) = hv;
    *(uint2*)((char*)lo + imgByte + off) = lv;
}

// ---------------- CSR build ----------------
__global__ void zero2_kernel(int* a, int* b, int n) {
    int i = blockIdx.x * blockDim.x + threadIdx.x;
    if (i < n) { a[i] = 0; b[i] = 0; }
}
__global__ void count_kernel(const int* __restrict__ ei, int* __restrict__ deg,
                             int* __restrict__ cnt) {
    int idx = blockIdx.x * blockDim.x + threadIdx.x;
    if (idx >= RR * EE) return;
    int r = idx / EE;
    int e = idx - r * EE;
    int src = ei[(size_t)r * 2 * EE + e];
    int dst = ei[(size_t)r * 2 * EE + EE + e];
    atomicAdd(&deg[r * NN + src], 1);
    atomicAdd(&cnt[r * NN + dst], 1);
}
__global__ void dinv_kernel(const int* __restrict__ deg, float* __restrict__ dinv) {
    int i = blockIdx.x * blockDim.x + threadIdx.x;
    if (i >= RR * NN) return;
    int d = deg[i];
    dinv[i] = (d > 0) ? rsqrtf((float)d) : 0.0f;
}
__global__ void scan1_kernel(const int* __restrict__ in, int* __restrict__ out,
                             int* __restrict__ bsums, int n) {
    __shared__ int sh[1024];
    int i = blockIdx.x * 1024 + threadIdx.x;
    int v = (i < n) ? in[i] : 0;
    sh[threadIdx.x] = v;
    __syncthreads();
    for (int off = 1; off < 1024; off <<= 1) {
        int t = (threadIdx.x >= off) ? sh[threadIdx.x - off] : 0;
        __syncthreads();
        sh[threadIdx.x] += t;
        __syncthreads();
    }
    if (i < n) out[i] = sh[threadIdx.x] - v;
    if (threadIdx.x == 1023) bsums[blockIdx.x] = sh[1023];
}
__global__ void scan2_kernel(int* bsums, int nb) {
    __shared__ int sh[512];
    int v = (threadIdx.x < nb) ? bsums[threadIdx.x] : 0;
    sh[threadIdx.x] = v;
    __syncthreads();
    for (int off = 1; off < 512; off <<= 1) {
        int t = (threadIdx.x >= off) ? sh[threadIdx.x - off] : 0;
        __syncthreads();
        sh[threadIdx.x] += t;
        __syncthreads();
    }
    if (threadIdx.x < nb) bsums[threadIdx.x] = sh[threadIdx.x] - v;
}
__global__ void scan3_kernel(int* __restrict__ rp, const int* __restrict__ bsums,
                             int* __restrict__ cur, int n, int total) {
    int i = blockIdx.x * 1024 + threadIdx.x;
    if (i < n) {
        int v = rp[i] + bsums[blockIdx.x];
        rp[i] = v;
        cur[i] = v;
    }
    if (i == 0) rp[n] = total;
}
__global__ void fill_kernel(const int* __restrict__ ei, int* __restrict__ cur,
                            int* __restrict__ col) {
    int idx = blockIdx.x * blockDim.x + threadIdx.x;
    if (idx >= RR * EE) return;
    int r = idx / EE;
    int e = idx - r * EE;
    int src = ei[(size_t)r * 2 * EE + e];
    int dst = ei[(size_t)r * 2 * EE + EE + e];
    int pos = atomicAdd(&cur[r * NN + dst], 1);
    col[pos] = src;
}

// ---------------- weight preconversion (seg0 of cheb folds W0 - W2) ----------------
__global__ void preconv_kernel(const float* __restrict__ chebW,
                               const float* __restrict__ projW,
                               const float* __restrict__ W1,
                               __nv_bfloat16* __restrict__ Bhi,
                               __nv_bfloat16* __restrict__ Blo) {
    int idx = blockIdx.x * blockDim.x + threadIdx.x;
    if (idx >= NCH_TOTAL * 8192) return;
    int c = idx >> 13;
    int e = idx & 8191;
    int n = e >> 6;
    int kk = e & 63;
    const float* src;
    int kloc;
    if (c < 108)      { src = chebW + (size_t)(c / 6) * (KK * HH * HH); kloc = (c % 6) * 64; }
    else if (c < 120) { src = projW; kloc = (c - 108) * 64; }
    else              { src = W1;    kloc = (c - 120) * 64; }
    float v = src[(size_t)(kloc + kk) * HH + n];
    // Chebyshev fold: T2 = 2*P(T1) - h  =>  h coefficient becomes (W0 - W2)
    if (c < 108 && (c % 6) < 2)
        v -= src[(size_t)(kloc + kk + 256) * HH + n];
    __nv_bfloat16 hi = __float2bfloat16(v);
    __nv_bfloat16 lo = __float2bfloat16(v - __bfloat162float(hi));
    uint32_t off = SW128((uint32_t)(n * 128 + kk * 2)) >> 1;
    Bhi[(size_t)c * 8192 + off] = hi;
    Blo[(size_t)c * 8192 + off] = lo;
}

__global__ void xsplit_kernel(const float4* __restrict__ x,
                              __nv_bfloat16* __restrict__ hi, __nv_bfloat16* __restrict__ lo) {
    int t = blockIdx.x * blockDim.x + threadIdx.x;
    if (t >= NN * 32) return;
    int row = t >> 5;
    int lane = t & 31;
    float4 v = x[t];
    int tile = row >> 7;
    int mloc = row & 127;
    int p = lane >> 4;
    int kk = (lane * 4) & 63;
    split_store4(hi, lo, (size_t)(tile * 2 + p) * 16384, mloc, kk, v.x, v.y, v.z, v.w);
}

// ---------------- descriptors ----------------
struct Seg { const __nv_bfloat16* hi[6]; const __nv_bfloat16* lo[6]; };

struct PropBatch {
    const float4* hin[RR];
    float4* hout[RR];
    __nv_bfloat16 *Ohi[RR], *Olo[RR];
    float alpha;
};

struct GemmBatch {
    Seg A[RR];
    const __nv_bfloat16 *Bh[RR], *Bl[RR];
    const float* bias[RR];
    float* C[RR];
    __nv_bfloat16 *Ohi[RR], *Olo[RR];
    const float* auxW[RR];     // per-relation aux weight (128 floats), or null
    const float* auxB[RR];     // per-relation aux bias (1 float)
    float* auxOut[RR];         // aux output base (indexed by row), or null
};

// ---------------- prop body (R11 exact) ----------------
__device__ __forceinline__ void prop_body(const float4* __restrict__ hin,
                                          float4* __restrict__ hout,
                                          const int* __restrict__ rowptr,
                                          const int* __restrict__ col,
                                          const float* __restrict__ dinv,
                                          float alpha,
                                          __nv_bfloat16* __restrict__ Ohi,
                                          __nv_bfloat16* __restrict__ Olo, int vb) {
    int t = vb * 256 + threadIdx.x;
    int w = t >> 5;
    int lane = t & 31;
    if (w >= NN) return;
    int e = rowptr[w];
    int e1 = rowptr[w + 1];
    float4 acc = make_float4(0.f, 0.f, 0.f, 0.f);
    for (; e + 3 < e1; e += 4) {
        int s0 = __ldg(&col[e]);
        int s1 = __ldg(&col[e + 1]);
        int s2 = __ldg(&col[e + 2]);
        int s3 = __ldg(&col[e + 3]);
        float w0 = __ldg(&dinv[s0]);
        float w1 = __ldg(&dinv[s1]);
        float w2 = __ldg(&dinv[s2]);
        float w3 = __ldg(&dinv[s3]);
        float4 v0 = hin[(size_t)s0 * 32 + lane];
        float4 v1 = hin[(size_t)s1 * 32 + lane];
        float4 v2 = hin[(size_t)s2 * 32 + lane];
        float4 v3 = hin[(size_t)s3 * 32 + lane];
        acc.x += w0 * v0.x + w1 * v1.x + w2 * v2.x + w3 * v3.x;
        acc.y += w0 * v0.y + w1 * v1.y + w2 * v2.y + w3 * v3.y;
        acc.z += w0 * v0.z + w1 * v1.z + w2 * v2.z + w3 * v3.z;
        acc.w += w0 * v0.w + w1 * v1.w + w2 * v2.w + w3 * v3.w;
    }
    for (; e < e1; e++) {
        int s0 = __ldg(&col[e]);
        float w0 = __ldg(&dinv[s0]);
        float4 v0 = hin[(size_t)s0 * 32 + lane];
        acc.x += w0 * v0.x;
        acc.y += w0 * v0.y;
        acc.z += w0 * v0.z;
        acc.w += w0 * v0.w;
    }
    float sc = -alpha * dinv[w];
    float4 r;
    r.x = sc * acc.x; r.y = sc * acc.y; r.z = sc * acc.z; r.w = sc * acc.w;
    if (hout) hout[(size_t)w * 32 + lane] = r;
    int tile = w >> 7;
    int mloc = w & 127;
    int p = lane >> 4;
    int kk = (lane * 4) & 63;
    split_store4(Ohi, Olo, (size_t)(tile * 2 + p) * 16384, mloc, kk, r.x, r.y, r.z, r.w);
}

// ---------------- HMMA GEMM body (256 thr, 2 CTA/SM) + optional fused aux ----------------
__device__ __forceinline__ void gemm_body(const Seg& A, const __nv_bfloat16* __restrict__ Bhi,
                                          const __nv_bfloat16* __restrict__ Blo,
                                          const float* __restrict__ bias, float* __restrict__ C,
                                          __nv_bfloat16* __restrict__ Ohi,
                                          __nv_bfloat16* __restrict__ Olo,
                                          const float* __restrict__ auxW,
                                          const float* __restrict__ auxB,
                                          float* __restrict__ auxOut,
                                          int nchunks, int relu, int vb) {
    extern __shared__ char smem[];
    const uint32_t sb = smem_u32(smem);
    const int tid = threadIdx.x;
    const int wid = tid >> 5;
    const int lane = tid & 31;
    const int bm = vb * 128;
    const int mwarp = (wid >> 2) * 64;
    const int nwarp = (wid & 3) * 32;

    const int sel = lane >> 3;
    const int r8 = lane & 7;
    const int lm_roff = (sel & 1) * 8 + r8;
    const int lm_kbyte = (sel >> 1) * 16;

    float c[4][4][4];
#pragma unroll
    for (int i = 0; i < 4; i++)
#pragma unroll
        for (int j = 0; j < 4; j++)
#pragma unroll
            for (int q = 0; q < 4; q++) c[i][j][q] = 0.f;

    for (int ch = 0; ch < nchunks; ch++) {
        const int seg = ch >> 1, par = ch & 1;
        const char* pAh = (const char*)A.hi[seg] + (size_t)(vb * 2 + par) * 16384;
        const char* pAl = (const char*)A.lo[seg] + (size_t)(vb * 2 + par) * 16384;
        const char* pBh = (const char*)(Bhi + (size_t)ch * 8192);
        const char* pBl = (const char*)(Blo + (size_t)ch * 8192);
#pragma unroll
        for (int it = 0; it < 4; it++) {
            uint32_t q = (uint32_t)(it * 256 + tid) * 16;
            cpa16(sb + q,         pAh + q);
            cpa16(sb + 16384 + q, pAl + q);
            cpa16(sb + 32768 + q, pBh + q);
            cpa16(sb + 49152 + q, pBl + q);
        }
        asm volatile("cp.async.commit_group;");
        asm volatile("cp.async.wait_group 0;");
        __syncthreads();

#pragma unroll
        for (int ks = 0; ks < 4; ks++) {
            const int kb = ks * 32 + lm_kbyte;
            uint32_t afr[16], bfr[8];
#pragma unroll
            for (int g = 0; g < 2; g++)
                ldsm4(bfr + g * 4,
                      sb + 49152 + SW128((uint32_t)((nwarp + g * 16 + lm_roff) * 128 + kb)));
#pragma unroll
            for (int mt = 0; mt < 4; mt++)
                ldsm4(afr + mt * 4,
                      sb + SW128((uint32_t)((mwarp + mt * 16 + lm_roff) * 128 + kb)));
            // Ahi * Blo
#pragma unroll
            for (int mt = 0; mt < 4; mt++)
#pragma unroll
                for (int nt = 0; nt < 4; nt++)
                    mma16816(c[mt][nt], afr + mt * 4,
                             bfr[(nt >> 1) * 4 + (nt & 1)], bfr[(nt >> 1) * 4 + 2 + (nt & 1)]);
#pragma unroll
            for (int g = 0; g < 2; g++)
                ldsm4(bfr + g * 4,
                      sb + 32768 + SW128((uint32_t)((nwarp + g * 16 + lm_roff) * 128 + kb)));
            // Ahi * Bhi
#pragma unroll
            for (int mt = 0; mt < 4; mt++)
#pragma unroll
                for (int nt = 0; nt < 4; nt++)
                    mma16816(c[mt][nt], afr + mt * 4,
                             bfr[(nt >> 1) * 4 + (nt & 1)], bfr[(nt >> 1) * 4 + 2 + (nt & 1)]);
#pragma unroll
            for (int mt = 0; mt < 4; mt++)
                ldsm4(afr + mt * 4,
                      sb + 16384 + SW128((uint32_t)((mwarp + mt * 16 + lm_roff) * 128 + kb)));
            // Alo * Bhi
#pragma unroll
            for (int mt = 0; mt < 4; mt++)
#pragma unroll
                for (int nt = 0; nt < 4; nt++)
                    mma16816(c[mt][nt], afr + mt * 4,
                             bfr[(nt >> 1) * 4 + (nt & 1)], bfr[(nt >> 1) * 4 + 2 + (nt & 1)]);
        }
        __syncthreads();
    }

    const int crow = lane >> 2;
    const int ccol = (lane & 3) * 2;

    float* saux = (float*)smem;
    if (auxOut) {
        if (tid < 128) saux[tid] = 0.f;
        __syncthreads();
    }

#pragma unroll
    for (int mt = 0; mt < 4; mt++) {
#pragma unroll
        for (int half = 0; half < 2; half++) {
            int mloc = mwarp + mt * 16 + crow + half * 8;
            int gm = bm + mloc;
            float ap = 0.f;
#pragma unroll
            for (int nt = 0; nt < 4; nt++) {
                int gn = nwarp + nt * 8 + ccol;
                float v0 = c[mt][nt][half * 2 + 0] + bias[gn];
                float v1 = c[mt][nt][half * 2 + 1] + bias[gn + 1];
                if (relu) { v0 = fmaxf(v0, 0.f); v1 = fmaxf(v1, 0.f); }
                if (gm < NN) {
                    if (C) {
                        float2 o; o.x = v0; o.y = v1;
                        *(float2*)(C + (size_t)gm * HH + gn) = o;
                    }
                    if (Ohi) {
                        __nv_bfloat162 h2, l2;
                        h2.x = __float2bfloat16(v0);
                        h2.y = __float2bfloat16(v1);
                        l2.x = __float2bfloat16(v0 - __bfloat162float(h2.x));
                        l2.y = __float2bfloat16(v1 - __bfloat162float(h2.y));
                        int p = gn >> 6;
                        int kk = gn & 63;
                        size_t imgB = (size_t)(vb * 2 + p) * 16384;
                        uint32_t off = SW128((uint32_t)(mloc * 128 + kk * 2));
                        *(uint32_t*)((char*)Ohi + imgB + off) = *(uint32_t*)&h2;
                        *(uint32_t*)((char*)Olo + imgB + off) = *(uint32_t*)&l2;
                    }
                }
                if (auxOut) ap += v0 * auxW[gn] + v1 * auxW[gn + 1];
            }
            if (auxOut) {
                // quad lanes (same crow, consecutive ccol) hold the same row
                ap += __shfl_xor_sync(0xFFFFFFFFu, ap, 1);
                ap += __shfl_xor_sync(0xFFFFFFFFu, ap, 2);
                if (gm < NN && (lane & 3) == 0)
                    atomicAdd(&saux[mloc], ap);
            }
        }
    }

    if (auxOut) {
        __syncthreads();
        if (tid < 128 && bm + tid < NN)
            auxOut[bm + tid] = saux[tid] + auxB[0];
    }
}

// ---------------- batched kernels ----------------
__global__ void propb_kernel(PropBatch pb, const int* __restrict__ rp,
                             const int* __restrict__ col, const float* __restrict__ dinvAll) {
    int r = blockIdx.x / PROP_BLOCKS;
    int vb = blockIdx.x - r * PROP_BLOCKS;
    prop_body(pb.hin[r], pb.hout[r], rp + r * NN, col, dinvAll + r * NN,
              pb.alpha, pb.Ohi[r], pb.Olo[r], vb);
}

__global__ __launch_bounds__(256, 2)
void gemmb_kernel(GemmBatch gb, int nchunks, int relu) {
    int r = blockIdx.x / NT;
    int vb = blockIdx.x - r * NT;
    gemm_body(gb.A[r], gb.Bh[r], gb.Bl[r], gb.bias[r], gb.C[r],
              gb.Ohi[r], gb.Olo[r], gb.auxW[r], gb.auxB[r], gb.auxOut[r],
              nchunks, relu, vb);
}

__global__ __launch_bounds__(256, 2)
void gemm_mma(Seg A, const __nv_bfloat16* __restrict__ Bhi,
              const __nv_bfloat16* __restrict__ Blo,
              const float* __restrict__ bias, float* __restrict__ C,
              __nv_bfloat16* __restrict__ Ohi, __nv_bfloat16* __restrict__ Olo,
              int nchunks, int relu) {
    gemm_body(A, Bhi, Blo, bias, C, Ohi, Olo, nullptr, nullptr, nullptr,
              nchunks, relu, blockIdx.x);
}

// ---------------- final: logit only ----------------
__global__ void final_kernel(const float4* __restrict__ hc,
                             const float* __restrict__ clsW2, const float* __restrict__ clsb2,
                             float* __restrict__ out) {
    int t = blockIdx.x * blockDim.x + threadIdx.x;
    int gw = t >> 5;
    int lane = t & 31;
    if (gw >= NN) return;
    float4 a = hc[(size_t)gw * 32 + lane];
    float4 w = ((const float4*)clsW2)[lane];
    float s = a.x * w.x + a.y * w.y + a.z * w.z + a.w * w.w;
#pragma unroll
    for (int off = 16; off; off >>= 1) s += __shfl_xor_sync(0xFFFFFFFFu, s, off);
    if (lane == 0) out[gw] = s + clsb2[0];
}

// ---------------- launch ----------------
extern "C" void kernel_launch(void* const* d_in, const int* in_sizes, int n_in,
                              void* d_out, int out_size) {
    (void)in_sizes; (void)n_in; (void)out_size;
    const float* x     = (const float*)d_in[0];
    const int*   ei    = (const int*)d_in[1];
    const float* chebW = (const float*)d_in[2];
    const float* chebB = (const float*)d_in[3];
    const float* projW = (const float*)d_in[4];
    const float* projB = (const float*)d_in[5];
    const float* W1    = (const float*)d_in[6];
    const float* b1    = (const float*)d_in[7];
    const float* W2    = (const float*)d_in[8];
    const float* b2    = (const float*)d_in[9];
    const float* auxW  = (const float*)d_in[10];
    const float* auxB  = (const float*)d_in[11];
    float* out = (float*)d_out;

    float *txF, *hAf, *hBf, *dinv;
    int *deg, *cnt, *rp, *cur, *col, *bs;
    __nv_bfloat16 *Bhi, *Blo, *xsh, *xsl, *rimg, *esh, *esl;
    cudaGetSymbolAddress((void**)&txF, g_txF);
    cudaGetSymbolAddress((void**)&hAf, g_hAf);
    cudaGetSymbolAddress((void**)&hBf, g_hBf);
    cudaGetSymbolAddress((void**)&dinv, g_dinv);
    cudaGetSymbolAddress((void**)&deg, g_deg);
    cudaGetSymbolAddress((void**)&cnt, g_cnt);
    cudaGetSymbolAddress((void**)&rp, g_rp);
    cudaGetSymbolAddress((void**)&cur, g_cur);
    cudaGetSymbolAddress((void**)&col, g_col);
    cudaGetSymbolAddress((void**)&bs, g_bsums);
    cudaGetSymbolAddress((void**)&Bhi, g_Bhi);
    cudaGetSymbolAddress((void**)&Blo, g_Blo);
    cudaGetSymbolAddress((void**)&xsh, g_xs_hi);
    cudaGetSymbolAddress((void**)&xsl, g_xs_lo);
    cudaGetSymbolAddress((void**)&rimg, g_rimg);
    cudaGetSymbolAddress((void**)&esh, g_es_hi);
    cudaGetSymbolAddress((void**)&esl, g_es_lo);

    const int SMEM_BYTES = 65536;
    cudaFuncSetAttribute(gemm_mma, cudaFuncAttributeMaxDynamicSharedMemorySize, SMEM_BYTES);
    cudaFuncSetAttribute(gemmb_kernel, cudaFuncAttributeMaxDynamicSharedMemorySize, SMEM_BYTES);

    // ---- serial head ----
    zero2_kernel<<<(RR * NN + 255) / 256, 256>>>(deg, cnt, RR * NN);
    count_kernel<<<(RR * EE + 255) / 256, 256>>>(ei, deg, cnt);
    dinv_kernel<<<(RR * NN + 255) / 256, 256>>>(deg, dinv);
    const int ntot = RR * NN;
    const int nb = (ntot + 1023) / 1024;
    scan1_kernel<<<nb, 1024>>>(cnt, rp, bs, ntot);
    scan2_kernel<<<1, 512>>>(bs, nb);
    scan3_kernel<<<nb, 1024>>>(rp, bs, cur, ntot, RR * EE);
    fill_kernel<<<(RR * EE + 255) / 256, 256>>>(ei, cur, col);
    preconv_kernel<<<(NCH_TOTAL * 8192 + 255) / 256, 256>>>(chebW, projW, W1, Bhi, Blo);
    xsplit_kernel<<<(NN * 32 + 255) / 256, 256>>>((const float4*)x, xsh, xsl);

    // ---- per-relation pointer tables ----
    const float* h_fp32[RR][LL];
    const __nv_bfloat16 *h_hi[RR][LL], *h_lo[RR][LL];
    float* g_out[RR][LL];
    __nv_bfloat16 *g_oh[RR][LL], *g_ol[RR][LL];
    __nv_bfloat16 *txh_[RR], *txl_[RR], *tx2h_[RR], *tx2l_[RR];
    float* txr_[RR];
    for (int r = 0; r < RR; r++) {
        __nv_bfloat16* ri = rimg + (size_t)r * 8 * IMG_ELEMS;
        txh_[r] = ri;                  txl_[r] = ri + IMG_ELEMS;
        tx2h_[r] = ri + 2 * IMG_ELEMS; tx2l_[r] = ri + 3 * IMG_ELEMS;
        __nv_bfloat16 *hAh = ri + 4 * IMG_ELEMS, *hAl = ri + 5 * IMG_ELEMS;
        __nv_bfloat16 *hBh = ri + 6 * IMG_ELEMS, *hBl = ri + 7 * IMG_ELEMS;
        txr_[r] = txF + (size_t)r * NHE;
        h_fp32[r][0] = x;  h_hi[r][0] = xsh; h_lo[r][0] = xsl;
        g_out[r][0] = hAf + (size_t)r * NHE; g_oh[r][0] = hAh; g_ol[r][0] = hAl;
        g_out[r][1] = hBf + (size_t)r * NHE; g_oh[r][1] = hBh; g_ol[r][1] = hBl;
        g_out[r][2] = nullptr;   // emb fp32 is dead: aux fused into epilogue, proj uses images
        g_oh[r][2] = esh + (size_t)r * IMG_ELEMS;
        g_ol[r][2] = esl + (size_t)r * IMG_ELEMS;
        for (int l = 1; l < LL; l++) {
            h_fp32[r][l] = g_out[r][l - 1];
            h_hi[r][l] = g_oh[r][l - 1];
            h_lo[r][l] = g_ol[r][l - 1];
        }
    }

    // ---- layer loop: batched across relations ----
    for (int l = 0; l < LL; l++) {
        PropBatch p1;
        p1.alpha = 1.0f;
        for (int r = 0; r < RR; r++) {
            p1.hin[r] = (const float4*)h_fp32[r][l];
            p1.hout[r] = (float4*)txr_[r];
            p1.Ohi[r] = txh_[r]; p1.Olo[r] = txl_[r];
        }
        propb_kernel<<<RR * PROP_BLOCKS, 256>>>(p1, rp, col, dinv);

        PropBatch p2;
        p2.alpha = 2.0f;   // tx2' = 2*P(tx); the -h term is folded into seg0 weights
        for (int r = 0; r < RR; r++) {
            p2.hin[r] = (const float4*)txr_[r];
            p2.hout[r] = nullptr;
            p2.Ohi[r] = tx2h_[r]; p2.Olo[r] = tx2l_[r];
        }
        propb_kernel<<<RR * PROP_BLOCKS, 256>>>(p2, rp, col, dinv);

        GemmBatch gb;
        for (int r = 0; r < RR; r++) {
            for (int i = 0; i < 6; i++) { gb.A[r].hi[i] = nullptr; gb.A[r].lo[i] = nullptr; }
            gb.A[r].hi[0] = h_hi[r][l];  gb.A[r].lo[0] = h_lo[r][l];
            gb.A[r].hi[1] = txh_[r];     gb.A[r].lo[1] = txl_[r];
            gb.A[r].hi[2] = tx2h_[r];    gb.A[r].lo[2] = tx2l_[r];
            int g = r * LL + l;
            gb.Bh[r] = Bhi + (size_t)(g * 6) * 8192;
            gb.Bl[r] = Blo + (size_t)(g * 6) * 8192;
            gb.bias[r] = chebB + (size_t)g * HH;
            gb.C[r] = g_out[r][l];
            gb.Ohi[r] = g_oh[r][l];
            gb.Olo[r] = g_ol[r][l];
            if (l == LL - 1) {
                gb.auxW[r] = auxW + (size_t)r * HH;
                gb.auxB[r] = auxB + r;
                gb.auxOut[r] = out + NN + (size_t)r * NN;   // aux block of d_out
            } else {
                gb.auxW[r] = nullptr;
                gb.auxB[r] = nullptr;
                gb.auxOut[r] = nullptr;
            }
        }
        gemmb_kernel<<<RR * NT, 256, SMEM_BYTES>>>(gb, 6, 1);
    }

    // ---- serial tail ----
    __nv_bfloat16* ri0 = rimg;   // relation-0 tx images, dead now -> scratch for hp
    Seg sp;
    for (int r = 0; r < RR; r++) {
        sp.hi[r] = esh + (size_t)r * IMG_ELEMS;
        sp.lo[r] = esl + (size_t)r * IMG_ELEMS;
    }
    gemm_mma<<<NT, 256, SMEM_BYTES>>>(sp, Bhi + (size_t)108 * 8192,
        Blo + (size_t)108 * 8192, projB, (float*)nullptr, ri0, ri0 + IMG_ELEMS, 12, 1);

    Seg s1;
    s1.hi[0] = ri0; s1.lo[0] = ri0 + IMG_ELEMS;
    for (int i = 1; i < 6; i++) { s1.hi[i] = nullptr; s1.lo[i] = nullptr; }
    gemm_mma<<<NT, 256, SMEM_BYTES>>>(s1, Bhi + (size_t)120 * 8192,
        Blo + (size_t)120 * 8192, b1, hBf,
        (__nv_bfloat16*)nullptr, (__nv_bfloat16*)nullptr, 2, 1);

    final_kernel<<<(NN * 32 + 255) / 256, 256>>>((const float4*)hBf, W2, b2, out);
}